// round 1
// baseline (speedup 1.0000x reference)
#include <cuda_runtime.h>
#include <math.h>

#define NBLK 1184
#define NTHR 256
#define NCOL 256

// Per-block per-column partial sums of squares. ~1.2 MB static device scratch.
__device__ float g_partials[NBLK * NCOL];

__global__ void __launch_bounds__(NTHR, 4)
colsq_kernel(const float* __restrict__ d, long long n_f4) {
    const int tid = threadIdx.x;
    const float4* __restrict__ p = (const float4*)d;

    // Each iteration's column group is fixed per thread because the stride in
    // floats (gridDim*NTHR*4) is a multiple of NCOL=256.
    long long idx = (long long)blockIdx.x * NTHR + tid;
    const long long stride = (long long)gridDim.x * NTHR;

    float a0 = 0.f, a1 = 0.f, a2 = 0.f, a3 = 0.f;

    // Unroll x4 for MLP (independent in-flight LDG.128s).
    long long i = idx;
    for (; i + 3 * stride < n_f4; i += 4 * stride) {
        float4 v0 = p[i];
        float4 v1 = p[i + stride];
        float4 v2 = p[i + 2 * stride];
        float4 v3 = p[i + 3 * stride];
        a0 += v0.x * v0.x; a1 += v0.y * v0.y; a2 += v0.z * v0.z; a3 += v0.w * v0.w;
        a0 += v1.x * v1.x; a1 += v1.y * v1.y; a2 += v1.z * v1.z; a3 += v1.w * v1.w;
        a0 += v2.x * v2.x; a1 += v2.y * v2.y; a2 += v2.z * v2.z; a3 += v2.w * v2.w;
        a0 += v3.x * v3.x; a1 += v3.y * v3.y; a2 += v3.z * v3.z; a3 += v3.w * v3.w;
    }
    for (; i < n_f4; i += stride) {
        float4 v = p[i];
        a0 += v.x * v.x; a1 += v.y * v.y; a2 += v.z * v.z; a3 += v.w * v.w;
    }

    // Deterministic block reduction: 4 replicas of the 256-column vector.
    // Thread tid owns columns c..c+3 where c = (tid*4) & 255; replica = tid/64.
    __shared__ float s[4][NCOL];
    const int c = (tid * 4) & (NCOL - 1);
    const int rep = tid >> 6;  // 0..3
    s[rep][c + 0] = a0;
    s[rep][c + 1] = a1;
    s[rep][c + 2] = a2;
    s[rep][c + 3] = a3;
    __syncthreads();

    // One thread per column sums the 4 replicas and writes the block partial.
    float part = s[0][tid] + s[1][tid] + s[2][tid] + s[3][tid];
    g_partials[(long long)blockIdx.x * NCOL + tid] = part;
}

__global__ void __launch_bounds__(NTHR)
finalize_kernel(float* __restrict__ out, int nblk) {
    const int tid = threadIdx.x;  // one thread per column
    float s = 0.f;
    for (int b = 0; b < nblk; b++)
        s += g_partials[(long long)b * NCOL + tid];

    float diff = s - 1.0f;
    float v = diff * diff;

    __shared__ float red[NTHR];
    red[tid] = v;
    __syncthreads();
    for (int off = NTHR / 2; off > 0; off >>= 1) {
        if (tid < off) red[tid] += red[tid + off];
        __syncthreads();
    }
    if (tid == 0) out[0] = 0.001f * sqrtf(red[0]);
}

extern "C" void kernel_launch(void* const* d_in, const int* in_sizes, int n_in,
                              void* d_out, int out_size) {
    const float* d = (const float*)d_in[0];
    float* out = (float*)d_out;
    long long n = (long long)in_sizes[0];      // 262144 * 256
    long long n_f4 = n / 4;

    colsq_kernel<<<NBLK, NTHR>>>(d, n_f4);
    finalize_kernel<<<1, NTHR>>>(out, NBLK);
}

// round 2
// speedup vs baseline: 1.6840x; 1.6840x over previous
#include <cuda_runtime.h>
#include <math.h>

#define NBLK 304          // 2 CTAs per SM on 152-SM GB300, single wave
#define NTHR 256
#define NCOL 256

// Per-block per-column partial sums of squares (304 KB static scratch).
__device__ float g_partials[NBLK * NCOL];

__global__ void __launch_bounds__(NTHR, 2)
colsq_kernel(const float* __restrict__ d, long long n_f4) {
    const int tid = threadIdx.x;
    const float4* __restrict__ p = (const float4*)d;

    // Stride in floats = gridDim*NTHR*4 = 304*256*4, a multiple of 256,
    // so every thread touches a fixed 4-column group.
    long long idx = (long long)blockIdx.x * NTHR + tid;
    const long long stride = (long long)gridDim.x * NTHR;

    float a0 = 0.f, a1 = 0.f, a2 = 0.f, a3 = 0.f;

    // Unroll x8: 8 independent LDG.128 in flight per thread.
    long long i = idx;
    for (; i + 7 * stride < n_f4; i += 8 * stride) {
        float4 v0 = p[i];
        float4 v1 = p[i + stride];
        float4 v2 = p[i + 2 * stride];
        float4 v3 = p[i + 3 * stride];
        float4 v4 = p[i + 4 * stride];
        float4 v5 = p[i + 5 * stride];
        float4 v6 = p[i + 6 * stride];
        float4 v7 = p[i + 7 * stride];
        a0 += v0.x * v0.x; a1 += v0.y * v0.y; a2 += v0.z * v0.z; a3 += v0.w * v0.w;
        a0 += v1.x * v1.x; a1 += v1.y * v1.y; a2 += v1.z * v1.z; a3 += v1.w * v1.w;
        a0 += v2.x * v2.x; a1 += v2.y * v2.y; a2 += v2.z * v2.z; a3 += v2.w * v2.w;
        a0 += v3.x * v3.x; a1 += v3.y * v3.y; a2 += v3.z * v3.z; a3 += v3.w * v3.w;
        a0 += v4.x * v4.x; a1 += v4.y * v4.y; a2 += v4.z * v4.z; a3 += v4.w * v4.w;
        a0 += v5.x * v5.x; a1 += v5.y * v5.y; a2 += v5.z * v5.z; a3 += v5.w * v5.w;
        a0 += v6.x * v6.x; a1 += v6.y * v6.y; a2 += v6.z * v6.z; a3 += v6.w * v6.w;
        a0 += v7.x * v7.x; a1 += v7.y * v7.y; a2 += v7.z * v7.z; a3 += v7.w * v7.w;
    }
    for (; i < n_f4; i += stride) {
        float4 v = p[i];
        a0 += v.x * v.x; a1 += v.y * v.y; a2 += v.z * v.z; a3 += v.w * v.w;
    }

    // Deterministic block reduction: 4 replicas of the 256-column vector.
    __shared__ float s[4][NCOL];
    const int c = (tid * 4) & (NCOL - 1);
    const int rep = tid >> 6;  // 0..3
    s[rep][c + 0] = a0;
    s[rep][c + 1] = a1;
    s[rep][c + 2] = a2;
    s[rep][c + 3] = a3;
    __syncthreads();

    float part = s[0][tid] + s[1][tid] + s[2][tid] + s[3][tid];
    g_partials[(long long)blockIdx.x * NCOL + tid] = part;
}

// One block, 1024 threads: 4 threads per column, coalesced reads, MLP via unroll.
__global__ void __launch_bounds__(1024)
finalize_kernel(float* __restrict__ out, int nblk) {
    const int tid = threadIdx.x;
    const int col = tid & (NCOL - 1);
    const int r = tid >> 8;          // replica 0..3

    // Sum blocks b = r, r+4, r+8, ... (76 each), unrolled x4 for MLP.
    float s0 = 0.f, s1 = 0.f, s2 = 0.f, s3 = 0.f;
    int b = r;
    for (; b + 12 < nblk; b += 16) {
        s0 += g_partials[(b     ) * NCOL + col];
        s1 += g_partials[(b +  4) * NCOL + col];
        s2 += g_partials[(b +  8) * NCOL + col];
        s3 += g_partials[(b + 12) * NCOL + col];
    }
    for (; b < nblk; b += 4)
        s0 += g_partials[b * NCOL + col];
    float part = (s0 + s1) + (s2 + s3);

    __shared__ float sm[4][NCOL];
    sm[r][col] = part;
    __syncthreads();

    if (tid < NCOL) {
        float colsum = sm[0][tid] + sm[1][tid] + sm[2][tid] + sm[3][tid];
        float diff = colsum - 1.0f;
        sm[0][tid] = diff * diff;
    }
    __syncthreads();

    // Tree-reduce 256 values (threads 0..255 only; others idle at syncs).
    for (int off = NCOL / 2; off >= 32; off >>= 1) {
        if (tid < off) sm[0][tid] += sm[0][tid + off];
        __syncthreads();
    }
    if (tid < 32) {
        float v = sm[0][tid];
        #pragma unroll
        for (int off = 16; off > 0; off >>= 1)
            v += __shfl_down_sync(0xFFFFFFFF, v, off);
        if (tid == 0) out[0] = 0.001f * sqrtf(v);
    }
}

extern "C" void kernel_launch(void* const* d_in, const int* in_sizes, int n_in,
                              void* d_out, int out_size) {
    const float* d = (const float*)d_in[0];
    float* out = (float*)d_out;
    long long n = (long long)in_sizes[0];      // 262144 * 256
    long long n_f4 = n / 4;

    colsq_kernel<<<NBLK, NTHR>>>(d, n_f4);
    finalize_kernel<<<1, 1024>>>(out, NBLK);
}